// round 6
// baseline (speedup 1.0000x reference)
#include <cuda_runtime.h>
#include <math.h>

#define BATCH   4
#define N_SEQ   1024
#define D_MODEL 256
#define N_HEADS 8
#define D_HEAD  32
#define ATT_SCALE 0.17677669529663687f   // 1/sqrt(32)

// Scratch (device globals: no allocation allowed in kernel_launch)
__device__ float g_Q[BATCH * N_HEADS * N_SEQ * D_HEAD];   // [b,h,n,dk]  tf32, pre-scaled
__device__ float g_K[BATCH * N_HEADS * N_SEQ * D_HEAD];   // tf32-rounded
__device__ float g_V[BATCH * N_HEADS * N_SEQ * D_HEAD];   // tf32-rounded
__device__ float g_AO[BATCH * N_SEQ * D_MODEL];           // attention out, tf32-rounded
__device__ float g_maskval[BATCH * N_SEQ];                // 0 or -inf per key

__device__ __forceinline__ unsigned f2tf32(float f) {
    unsigned u;
    asm("cvt.rna.tf32.f32 %0, %1;" : "=r"(u) : "f"(f));
    return u;
}

#define MMA_TF32(d, a, b)                                                     \
    asm volatile(                                                             \
        "mma.sync.aligned.m16n8k8.row.col.f32.tf32.tf32.f32 "                 \
        "{%0,%1,%2,%3}, {%4,%5,%6,%7}, {%8,%9}, {%0,%1,%2,%3};\n"             \
        : "+f"((d)[0]), "+f"((d)[1]), "+f"((d)[2]), "+f"((d)[3])              \
        : "r"((a)[0]), "r"((a)[1]), "r"((a)[2]), "r"((a)[3]),                 \
          "r"((b)[0]), "r"((b)[1]))

__device__ __forceinline__ void cp_async16(void* s, const void* g) {
    unsigned sa = (unsigned)__cvta_generic_to_shared(s);
    asm volatile("cp.async.cg.shared.global [%0], [%1], 16;" :: "r"(sa), "l"(g));
}
#define CP_COMMIT() asm volatile("cp.async.commit_group;")
#define CP_WAIT0()  asm volatile("cp.async.wait_group 0;")
#define CP_WAIT1()  asm volatile("cp.async.wait_group 1;")
#define CP_WAIT2()  asm volatile("cp.async.wait_group 2;")

// ---------------------------------------------------------------------------
// Mask prep (parallel): detect storage dtype (int32 / float32 / uint8),
// expand to float additive mask (0 or -inf).
// ---------------------------------------------------------------------------
__global__ void prep_mask_kernel(const void* __restrict__ mraw) {
    const int tid = threadIdx.x;   // 256
    const unsigned* mi = (const unsigned*)mraw;
    int ok_int = 1, ok_float = 1;
    for (int i = tid; i < 1024; i += 256) {
        unsigned v = mi[i];
        if (v > 1u) ok_int = 0;
        if (v != 0u && v != 0x3F800000u) ok_float = 0;
    }
    int all_int   = __syncthreads_and(ok_int);
    int all_float = __syncthreads_and(ok_float);
    const int mode = all_int ? 0 : (all_float ? 1 : 2);
    const float NEG_INF = __int_as_float(0xff800000);
    for (int i = tid; i < BATCH * N_SEQ; i += 256) {
        int masked;
        if (mode == 0)      masked = ((const int*)mraw)[i] != 0;
        else if (mode == 1) masked = ((const unsigned*)mraw)[i] != 0u;
        else                masked = ((const unsigned char*)mraw)[i] != 0;
        g_maskval[i] = masked ? NEG_INF : 0.0f;
    }
}

// ---------------------------------------------------------------------------
// Fused QKV projection, tf32 tensor cores, 2-stage cp.async pipeline.
// grid=(64,4,3), block=128. Q additionally scaled by ATT_SCALE.
// ---------------------------------------------------------------------------
__global__ __launch_bounds__(128) void gemm_qkv_tc(
    const float* __restrict__ x,
    const float* __restrict__ Wq, const float* __restrict__ Wk, const float* __restrict__ Wv,
    const float* __restrict__ bq, const float* __restrict__ bk, const float* __restrict__ bv)
{
    __shared__ float As[2][64][36];
    __shared__ float Ws[2][64][36];

    const int z = blockIdx.z;
    const float* W    = (z == 0) ? Wq : (z == 1) ? Wk : Wv;
    const float* bias = (z == 0) ? bq : (z == 1) ? bk : bv;
    float* out        = (z == 0) ? g_Q : (z == 1) ? g_K : g_V;

    const int tid  = threadIdx.x;
    const int lane = tid & 31;
    const int w    = tid >> 5;
    const int g    = lane >> 2;
    const int t    = lane & 3;
    const int w16  = w * 16;
    const int rbase = blockIdx.x * 64;
    const int cbase = blockIdx.y * 64;

    float sc[8][4];
#pragma unroll
    for (int n = 0; n < 8; n++)
#pragma unroll
        for (int j = 0; j < 4; j++) sc[n][j] = 0.0f;

    auto prefetch = [&](int c) {
        const int k0 = c * 32, st = c & 1;
#pragma unroll
        for (int it = 0; it < 4; it++) {
            int s = it * 128 + tid;
            int row = s >> 3;
            int c4 = (s & 7) * 4;
            cp_async16(&As[st][row][c4], &x[(size_t)(rbase + row) * D_MODEL + k0 + c4]);
        }
#pragma unroll
        for (int it = 0; it < 4; it++) {
            int s = it * 128 + tid;
            int row = s >> 3;
            int c4 = (s & 7) * 4;
            cp_async16(&Ws[st][row][c4], &W[(size_t)(cbase + row) * D_MODEL + k0 + c4]);
        }
        CP_COMMIT();
    };

    prefetch(0);
    for (int c = 0; c < 8; c++) {
        const int st = c & 1;
        if (c < 7) { prefetch(c + 1); CP_WAIT1(); }
        else       { CP_WAIT0(); }
        __syncthreads();

        unsigned qa[4][4];
#pragma unroll
        for (int kk = 0; kk < 4; kk++) {
            qa[kk][0] = f2tf32(As[st][w16 + g    ][kk * 8 + t    ]);
            qa[kk][1] = f2tf32(As[st][w16 + g + 8][kk * 8 + t    ]);
            qa[kk][2] = f2tf32(As[st][w16 + g    ][kk * 8 + t + 4]);
            qa[kk][3] = f2tf32(As[st][w16 + g + 8][kk * 8 + t + 4]);
        }
#pragma unroll
        for (int n8 = 0; n8 < 8; n8++) {
#pragma unroll
            for (int kk = 0; kk < 4; kk++) {
                unsigned bb[2];
                bb[0] = f2tf32(Ws[st][n8 * 8 + g][kk * 8 + t    ]);
                bb[1] = f2tf32(Ws[st][n8 * 8 + g][kk * 8 + t + 4]);
                MMA_TF32(sc[n8], qa[kk], bb);
            }
        }
        __syncthreads();
    }

    const float scale = (z == 0) ? ATT_SCALE : 1.0f;
#pragma unroll
    for (int n8 = 0; n8 < 8; n8++) {
        int c0 = cbase + n8 * 8 + 2 * t;
        float b0v = bias[c0], b1v = bias[c0 + 1];
        int r0 = rbase + w16 + g;
        int r1 = r0 + 8;
        float2 v0, v1;
        v0.x = __uint_as_float(f2tf32((sc[n8][0] + b0v) * scale));
        v0.y = __uint_as_float(f2tf32((sc[n8][1] + b1v) * scale));
        v1.x = __uint_as_float(f2tf32((sc[n8][2] + b0v) * scale));
        v1.y = __uint_as_float(f2tf32((sc[n8][3] + b1v) * scale));
        int h = c0 >> 5, dk = c0 & 31;
        int b0i = r0 >> 10, n0 = r0 & 1023;
        int b1i = r1 >> 10, n1 = r1 & 1023;
        *(float2*)&out[(size_t)(((b0i << 3) + h) * N_SEQ + n0) * D_HEAD + dk] = v0;
        *(float2*)&out[(size_t)(((b1i << 3) + h) * N_SEQ + n1) * D_HEAD + dk] = v1;
    }
}

// ---------------------------------------------------------------------------
// Output projection, tf32 tensor cores, 2-stage cp.async pipeline.
// grid=(64,4), block=128. A = g_AO (already tf32-rounded).
// ---------------------------------------------------------------------------
__global__ __launch_bounds__(128) void gemm_o_tc(
    const float* __restrict__ W, const float* __restrict__ bias,
    float* __restrict__ out)
{
    __shared__ float As[2][64][36];
    __shared__ float Ws[2][64][36];

    const int tid  = threadIdx.x;
    const int lane = tid & 31;
    const int w    = tid >> 5;
    const int g    = lane >> 2;
    const int t    = lane & 3;
    const int w16  = w * 16;
    const int rbase = blockIdx.x * 64;
    const int cbase = blockIdx.y * 64;

    float sc[8][4];
#pragma unroll
    for (int n = 0; n < 8; n++)
#pragma unroll
        for (int j = 0; j < 4; j++) sc[n][j] = 0.0f;

    auto prefetch = [&](int c) {
        const int k0 = c * 32, st = c & 1;
#pragma unroll
        for (int it = 0; it < 4; it++) {
            int s = it * 128 + tid;
            int row = s >> 3;
            int c4 = (s & 7) * 4;
            cp_async16(&As[st][row][c4], &g_AO[(size_t)(rbase + row) * D_MODEL + k0 + c4]);
        }
#pragma unroll
        for (int it = 0; it < 4; it++) {
            int s = it * 128 + tid;
            int row = s >> 3;
            int c4 = (s & 7) * 4;
            cp_async16(&Ws[st][row][c4], &W[(size_t)(cbase + row) * D_MODEL + k0 + c4]);
        }
        CP_COMMIT();
    };

    prefetch(0);
    for (int c = 0; c < 8; c++) {
        const int st = c & 1;
        if (c < 7) { prefetch(c + 1); CP_WAIT1(); }
        else       { CP_WAIT0(); }
        __syncthreads();

        unsigned qa[4][4];
#pragma unroll
        for (int kk = 0; kk < 4; kk++) {
            qa[kk][0] = __float_as_uint(As[st][w16 + g    ][kk * 8 + t    ]);
            qa[kk][1] = __float_as_uint(As[st][w16 + g + 8][kk * 8 + t    ]);
            qa[kk][2] = __float_as_uint(As[st][w16 + g    ][kk * 8 + t + 4]);
            qa[kk][3] = __float_as_uint(As[st][w16 + g + 8][kk * 8 + t + 4]);
        }
#pragma unroll
        for (int n8 = 0; n8 < 8; n8++) {
#pragma unroll
            for (int kk = 0; kk < 4; kk++) {
                unsigned bb[2];
                bb[0] = f2tf32(Ws[st][n8 * 8 + g][kk * 8 + t    ]);
                bb[1] = f2tf32(Ws[st][n8 * 8 + g][kk * 8 + t + 4]);
                MMA_TF32(sc[n8], qa[kk], bb);
            }
        }
        __syncthreads();
    }

#pragma unroll
    for (int n8 = 0; n8 < 8; n8++) {
        int c0 = cbase + n8 * 8 + 2 * t;
        float b0v = bias[c0], b1v = bias[c0 + 1];
        int r0 = rbase + w16 + g;
        int r1 = r0 + 8;
        float2 v0, v1;
        v0.x = sc[n8][0] + b0v;  v0.y = sc[n8][1] + b1v;
        v1.x = sc[n8][2] + b0v;  v1.y = sc[n8][3] + b1v;
        *(float2*)&out[(size_t)r0 * D_MODEL + c0] = v0;
        *(float2*)&out[(size_t)r1 * D_MODEL + c0] = v1;
    }
}

// ---------------------------------------------------------------------------
// Tensor-core flash attention, DOUBLE-BUFFERED 2-stage cp.async pipeline for
// bias + K/V. grid=(16,32), block=128 (4 warps). 1 CTA/SM (165 KB smem).
// Steady state: group(i+1) is in flight during ALL of tile i's compute.
// Dynamic smem layout (floats):
//   KsB[2][64*36]  @ 0      (4608)
//   VsB[2][64*40]  @ 4608   (5120)
//   Ps  [64*68]    @ 9728   (4352)   (also Q staging in prologue)
//   BE  [2][64*68] @ 14080  (8704)
//   BS  [2][64*68] @ 22784  (8704)
//   BR  [2][64*68] @ 31488  (8704)
//   Msk [1024]     @ 40192  (1024)
// total 41216 floats = 164864 B
// ---------------------------------------------------------------------------
#define ATTN_SMEM_BYTES (41216 * 4)

__global__ __launch_bounds__(128) void attn_tc_kernel(
    const float* __restrict__ edge,
    const float* __restrict__ spat,
    const float* __restrict__ rnk)
{
    extern __shared__ float dsm[];
    float* KsB = dsm;
    float* VsB = dsm + 4608;
    float* Ps  = dsm + 9728;
    float* BE  = dsm + 14080;
    float* BS  = dsm + 22784;
    float* BR  = dsm + 31488;
    float* Msk = dsm + 40192;

    const int tid  = threadIdx.x;
    const int lane = tid & 31;
    const int w    = tid >> 5;
    const int g    = lane >> 2;
    const int t    = lane & 3;
    const int qb   = blockIdx.x * 64;
    const int bh   = blockIdx.y;
    const int b    = bh >> 3;
    const int h    = bh & 7;
    const int w16  = w * 16;

    const float* Kg0 = g_K + (size_t)bh * N_SEQ * D_HEAD;
    const float* Vg0 = g_V + (size_t)bh * N_SEQ * D_HEAD;
    const float* maskp = g_maskval + b * N_SEQ;
    const float* eg0 = edge + ((size_t)bh * N_SEQ + qb) * N_SEQ;
    const float* sg0 = spat + ((size_t)bh * N_SEQ + qb) * N_SEQ;
    const float* rg0 = rnk  + ((size_t)bh * N_SEQ + qb) * N_SEQ;

    // issue group for k-tile i into buffer i&1
    auto issue_group = [&](int i) {
        const int kb = i * 64;
        const int st = i & 1;
        const float* Kg = Kg0 + (size_t)kb * D_HEAD;
        const float* Vg = Vg0 + (size_t)kb * D_HEAD;
        float* Ka = KsB + st * 2304;
        float* Va = VsB + st * 2560;
#pragma unroll
        for (int it = 0; it < 4; it++) {
            int s = it * 128 + tid;
            int row = s >> 3;
            int c4 = (s & 7) * 4;
            cp_async16(&Ka[row * 36 + c4], &Kg[row * D_HEAD + c4]);
            cp_async16(&Va[row * 40 + c4], &Vg[row * D_HEAD + c4]);
        }
        float* be = BE + st * 4352;
        float* bs = BS + st * 4352;
        float* br = BR + st * 4352;
        const float* eg = eg0 + kb;
        const float* sg = sg0 + kb;
        const float* rg = rg0 + kb;
#pragma unroll
        for (int it = 0; it < 8; it++) {
            int s = it * 128 + tid;
            int row = s >> 4;
            int c4 = (s & 15) * 4;
            size_t go = (size_t)row * N_SEQ + c4;
            int so = row * 68 + c4;
            cp_async16(&be[so], &eg[go]);
            cp_async16(&bs[so], &sg[go]);
            cp_async16(&br[so], &rg[go]);
        }
        CP_COMMIT();
    };

    // ---- Prologue ----
    // group C1: Q tile (into Ps) + full mask row (into Msk)
    const float* Qg = g_Q + ((size_t)bh * N_SEQ + qb) * D_HEAD;
#pragma unroll
    for (int it = 0; it < 4; it++) {
        int s = it * 128 + tid;
        int row = s >> 3;
        int c4 = (s & 7) * 4;
        cp_async16(&Ps[row * 68 + c4], &Qg[row * D_HEAD + c4]);
    }
#pragma unroll
    for (int it = 0; it < 2; it++) {
        int idx = (it * 128 + tid) * 4;
        cp_async16(&Msk[idx], &maskp[idx]);
    }
    CP_COMMIT();
    issue_group(0);   // C2
    issue_group(1);   // C3

    CP_WAIT2();       // C1 (Q + mask) arrived; groups 0,1 may be pending
    __syncthreads();

    unsigned qa[4][4];
#pragma unroll
    for (int kk = 0; kk < 4; kk++) {
        qa[kk][0] = __float_as_uint(Ps[(w16 + g    ) * 68 + kk * 8 + t    ]);
        qa[kk][1] = __float_as_uint(Ps[(w16 + g + 8) * 68 + kk * 8 + t    ]);
        qa[kk][2] = __float_as_uint(Ps[(w16 + g    ) * 68 + kk * 8 + t + 4]);
        qa[kk][3] = __float_as_uint(Ps[(w16 + g + 8) * 68 + kk * 8 + t + 4]);
    }
    __syncthreads();   // everyone has Q frags before Ps is reused for P

    float o[4][4];
#pragma unroll
    for (int n = 0; n < 4; n++)
#pragma unroll
        for (int j = 0; j < 4; j++) o[n][j] = 0.0f;

    float m0 = __int_as_float(0xff800000), m1 = m0;
    float l0 = 0.0f, l1 = 0.0f;

    for (int i = 0; i < 16; i++) {
        const int kb = i * 64;
        const int st = i & 1;
        float* Ks = KsB + st * 2304;
        float* Vs = VsB + st * 2560;
        float* be = BE + st * 4352;
        float* bsp = BS + st * 4352;
        float* br = BR + st * 4352;

        // 1. group(i) arrived (group(i+1) may stay in flight the whole tile)
        if (i < 15) { CP_WAIT1(); } else { CP_WAIT0(); }
        __syncthreads();

        // 2. S = Q K^T (Q pre-scaled by ATT_SCALE)
        float sc[8][4];
#pragma unroll
        for (int n8 = 0; n8 < 8; n8++) {
            sc[n8][0] = sc[n8][1] = sc[n8][2] = sc[n8][3] = 0.0f;
#pragma unroll
            for (int kk = 0; kk < 4; kk++) {
                unsigned bb[2];
                bb[0] = __float_as_uint(Ks[(n8 * 8 + g) * 36 + kk * 8 + t    ]);
                bb[1] = __float_as_uint(Ks[(n8 * 8 + g) * 36 + kk * 8 + t + 4]);
                MMA_TF32(sc[n8], qa[kk], bb);
            }
        }

        // 3. combine biases + mask (all from smem)
#pragma unroll
        for (int n8 = 0; n8 < 8; n8++) {
            int c0 = n8 * 8 + 2 * t;
            int ro0 = (w16 + g    ) * 68 + c0;
            int ro1 = (w16 + g + 8) * 68 + c0;
            float2 e0 = *(float2*)&be[ro0],  e1 = *(float2*)&be[ro1];
            float2 s0 = *(float2*)&bsp[ro0], s1 = *(float2*)&bsp[ro1];
            float2 r0 = *(float2*)&br[ro0],  r1 = *(float2*)&br[ro1];
            float2 mk = *(float2*)&Msk[kb + c0];
            sc[n8][0] += (e0.x + s0.x) + (r0.x + mk.x);
            sc[n8][1] += (e0.y + s0.y) + (r0.y + mk.y);
            sc[n8][2] += (e1.x + s1.x) + (r1.x + mk.x);
            sc[n8][3] += (e1.y + s1.y) + (r1.y + mk.y);
        }

        // 4. online softmax
        float ml0 = sc[0][0], ml1 = sc[0][2];
#pragma unroll
        for (int n8 = 0; n8 < 8; n8++) {
            ml0 = fmaxf(ml0, fmaxf(sc[n8][0], sc[n8][1]));
            ml1 = fmaxf(ml1, fmaxf(sc[n8][2], sc[n8][3]));
        }
        ml0 = fmaxf(ml0, __shfl_xor_sync(0xffffffffu, ml0, 1));
        ml0 = fmaxf(ml0, __shfl_xor_sync(0xffffffffu, ml0, 2));
        ml1 = fmaxf(ml1, __shfl_xor_sync(0xffffffffu, ml1, 1));
        ml1 = fmaxf(ml1, __shfl_xor_sync(0xffffffffu, ml1, 2));

        float mn0 = fmaxf(m0, ml0);
        float mn1 = fmaxf(m1, ml1);
        float mc0 = fmaxf(mn0, -1e30f);
        float mc1 = fmaxf(mn1, -1e30f);
        float rs0 = __expf(fmaxf(m0, -1e30f) - mc0);
        float rs1 = __expf(fmaxf(m1, -1e30f) - mc1);
        m0 = mn0; m1 = mn1;

        float sum0 = 0.0f, sum1 = 0.0f;
#pragma unroll
        for (int n8 = 0; n8 < 8; n8++) {
            float p0 = __expf(sc[n8][0] - mc0);
            float p1 = __expf(sc[n8][1] - mc0);
            float p2 = __expf(sc[n8][2] - mc1);
            float p3 = __expf(sc[n8][3] - mc1);
            sum0 += p0 + p1;
            sum1 += p2 + p3;
            float2 w0, w1;
            w0.x = __uint_as_float(f2tf32(p0)); w0.y = __uint_as_float(f2tf32(p1));
            w1.x = __uint_as_float(f2tf32(p2)); w1.y = __uint_as_float(f2tf32(p3));
            *(float2*)&Ps[(w16 + g    ) * 68 + n8 * 8 + 2 * t] = w0;
            *(float2*)&Ps[(w16 + g + 8) * 68 + n8 * 8 + 2 * t] = w1;
        }
        sum0 += __shfl_xor_sync(0xffffffffu, sum0, 1);
        sum0 += __shfl_xor_sync(0xffffffffu, sum0, 2);
        sum1 += __shfl_xor_sync(0xffffffffu, sum1, 1);
        sum1 += __shfl_xor_sync(0xffffffffu, sum1, 2);
        l0 = l0 * rs0 + sum0;
        l1 = l1 * rs1 + sum1;

#pragma unroll
        for (int n = 0; n < 4; n++) {
            o[n][0] *= rs0; o[n][1] *= rs0;
            o[n][2] *= rs1; o[n][3] *= rs1;
        }

        __syncwarp();   // this warp's Ps rows visible warp-wide

        // 5. O += P V
#pragma unroll
        for (int kk = 0; kk < 8; kk++) {
            unsigned pa[4];
            pa[0] = __float_as_uint(Ps[(w16 + g    ) * 68 + kk * 8 + t    ]);
            pa[1] = __float_as_uint(Ps[(w16 + g + 8) * 68 + kk * 8 + t    ]);
            pa[2] = __float_as_uint(Ps[(w16 + g    ) * 68 + kk * 8 + t + 4]);
            pa[3] = __float_as_uint(Ps[(w16 + g + 8) * 68 + kk * 8 + t + 4]);
#pragma unroll
            for (int n = 0; n < 4; n++) {
                unsigned bb[2];
                bb[0] = __float_as_uint(Vs[(kk * 8 + t    ) * 40 + n * 8 + g]);
                bb[1] = __float_as_uint(Vs[(kk * 8 + t + 4) * 40 + n * 8 + g]);
                MMA_TF32(o[n], pa, bb);
            }
        }

        // 6. buffers of tile i fully consumed -> refill with group(i+2)
        __syncthreads();
        if (i < 14) issue_group(i + 2);
    }

    // normalize + scatter (tf32-rounded for the O-projection mma)
    float inv0 = (l0 > 0.0f) ? (1.0f / l0) : 0.0f;
    float inv1 = (l1 > 0.0f) ? (1.0f / l1) : 0.0f;
    const int r0 = qb + w16 + g;
    const int r1 = r0 + 8;
#pragma unroll
    for (int n = 0; n < 4; n++) {
        int d = n * 8 + 2 * t;
        float2 v0, v1;
        v0.x = __uint_as_float(f2tf32(o[n][0] * inv0));
        v0.y = __uint_as_float(f2tf32(o[n][1] * inv0));
        v1.x = __uint_as_float(f2tf32(o[n][2] * inv1));
        v1.y = __uint_as_float(f2tf32(o[n][3] * inv1));
        *(float2*)&g_AO[((size_t)(b * N_SEQ + r0)) * D_MODEL + h * D_HEAD + d] = v0;
        *(float2*)&g_AO[((size_t)(b * N_SEQ + r1)) * D_MODEL + h * D_HEAD + d] = v1;
    }
}

// ---------------------------------------------------------------------------
extern "C" void kernel_launch(void* const* d_in, const int* in_sizes, int n_in,
                              void* d_out, int out_size)
{
    const float* x    = (const float*)d_in[0];
    const float* edge = (const float*)d_in[1];
    const float* spat = (const float*)d_in[2];
    const float* rnk  = (const float*)d_in[3];
    const void*  mask = d_in[4];
    const float* Wq = (const float*)d_in[5];
    const float* bq = (const float*)d_in[6];
    const float* Wk = (const float*)d_in[7];
    const float* bk = (const float*)d_in[8];
    const float* Wv = (const float*)d_in[9];
    const float* bv = (const float*)d_in[10];
    const float* Wo = (const float*)d_in[11];
    const float* bo = (const float*)d_in[12];

    cudaFuncSetAttribute(attn_tc_kernel,
                         cudaFuncAttributeMaxDynamicSharedMemorySize,
                         ATTN_SMEM_BYTES);

    prep_mask_kernel<<<1, 256>>>(mask);

    gemm_qkv_tc<<<dim3(64, 4, 3), 128>>>(x, Wq, Wk, Wv, bq, bk, bv);

    attn_tc_kernel<<<dim3(16, 32), 128, ATTN_SMEM_BYTES>>>(edge, spat, rnk);

    gemm_o_tc<<<dim3(64, 4), 128>>>(Wo, bo, (float*)d_out);
}

// round 7
// speedup vs baseline: 1.1478x; 1.1478x over previous
#include <cuda_runtime.h>
#include <math.h>

#define BATCH   4
#define N_SEQ   1024
#define D_MODEL 256
#define N_HEADS 8
#define D_HEAD  32
#define ATT_SCALE 0.17677669529663687f   // 1/sqrt(32)

// Scratch (device globals: no allocation allowed in kernel_launch)
__device__ float g_Q[BATCH * N_HEADS * N_SEQ * D_HEAD];   // [b,h,n,dk]  tf32, pre-scaled
__device__ float g_K[BATCH * N_HEADS * N_SEQ * D_HEAD];   // tf32-rounded
__device__ float g_V[BATCH * N_HEADS * N_SEQ * D_HEAD];   // tf32-rounded
__device__ float g_AO[BATCH * N_SEQ * D_MODEL];           // attention out, tf32-rounded
__device__ float g_maskval[BATCH * N_SEQ];                // 0 or -inf per key

__device__ __forceinline__ unsigned f2tf32(float f) {
    unsigned u;
    asm("cvt.rna.tf32.f32 %0, %1;" : "=r"(u) : "f"(f));
    return u;
}

#define MMA_TF32(d, a, b)                                                     \
    asm volatile(                                                             \
        "mma.sync.aligned.m16n8k8.row.col.f32.tf32.tf32.f32 "                 \
        "{%0,%1,%2,%3}, {%4,%5,%6,%7}, {%8,%9}, {%0,%1,%2,%3};\n"             \
        : "+f"((d)[0]), "+f"((d)[1]), "+f"((d)[2]), "+f"((d)[3])              \
        : "r"((a)[0]), "r"((a)[1]), "r"((a)[2]), "r"((a)[3]),                 \
          "r"((b)[0]), "r"((b)[1]))

__device__ __forceinline__ void cp_async16(void* s, const void* g) {
    unsigned sa = (unsigned)__cvta_generic_to_shared(s);
    asm volatile("cp.async.cg.shared.global [%0], [%1], 16;" :: "r"(sa), "l"(g));
}
#define CP_COMMIT() asm volatile("cp.async.commit_group;")
#define CP_WAIT0()  asm volatile("cp.async.wait_group 0;")
#define CP_WAIT1()  asm volatile("cp.async.wait_group 1;")
#define CP_WAIT2()  asm volatile("cp.async.wait_group 2;")
#define CP_WAIT3()  asm volatile("cp.async.wait_group 3;")

// ---------------------------------------------------------------------------
// Mask prep (parallel): detect storage dtype (int32 / float32 / uint8),
// expand to float additive mask (0 or -inf).
// ---------------------------------------------------------------------------
__global__ void prep_mask_kernel(const void* __restrict__ mraw) {
    const int tid = threadIdx.x;   // 256
    const unsigned* mi = (const unsigned*)mraw;
    int ok_int = 1, ok_float = 1;
    for (int i = tid; i < 1024; i += 256) {
        unsigned v = mi[i];
        if (v > 1u) ok_int = 0;
        if (v != 0u && v != 0x3F800000u) ok_float = 0;
    }
    int all_int   = __syncthreads_and(ok_int);
    int all_float = __syncthreads_and(ok_float);
    const int mode = all_int ? 0 : (all_float ? 1 : 2);
    const float NEG_INF = __int_as_float(0xff800000);
    for (int i = tid; i < BATCH * N_SEQ; i += 256) {
        int masked;
        if (mode == 0)      masked = ((const int*)mraw)[i] != 0;
        else if (mode == 1) masked = ((const unsigned*)mraw)[i] != 0u;
        else                masked = ((const unsigned char*)mraw)[i] != 0;
        g_maskval[i] = masked ? NEG_INF : 0.0f;
    }
}

// ---------------------------------------------------------------------------
// Fused QKV projection, tf32 tensor cores, 2-stage cp.async pipeline.
// grid=(64,4,3), block=128. Q additionally scaled by ATT_SCALE.
// ---------------------------------------------------------------------------
__global__ __launch_bounds__(128) void gemm_qkv_tc(
    const float* __restrict__ x,
    const float* __restrict__ Wq, const float* __restrict__ Wk, const float* __restrict__ Wv,
    const float* __restrict__ bq, const float* __restrict__ bk, const float* __restrict__ bv)
{
    __shared__ float As[2][64][36];
    __shared__ float Ws[2][64][36];

    const int z = blockIdx.z;
    const float* W    = (z == 0) ? Wq : (z == 1) ? Wk : Wv;
    const float* bias = (z == 0) ? bq : (z == 1) ? bk : bv;
    float* out        = (z == 0) ? g_Q : (z == 1) ? g_K : g_V;

    const int tid  = threadIdx.x;
    const int lane = tid & 31;
    const int w    = tid >> 5;
    const int g    = lane >> 2;
    const int t    = lane & 3;
    const int w16  = w * 16;
    const int rbase = blockIdx.x * 64;
    const int cbase = blockIdx.y * 64;

    float sc[8][4];
#pragma unroll
    for (int n = 0; n < 8; n++)
#pragma unroll
        for (int j = 0; j < 4; j++) sc[n][j] = 0.0f;

    auto prefetch = [&](int c) {
        const int k0 = c * 32, st = c & 1;
#pragma unroll
        for (int it = 0; it < 4; it++) {
            int s = it * 128 + tid;
            int row = s >> 3;
            int c4 = (s & 7) * 4;
            cp_async16(&As[st][row][c4], &x[(size_t)(rbase + row) * D_MODEL + k0 + c4]);
        }
#pragma unroll
        for (int it = 0; it < 4; it++) {
            int s = it * 128 + tid;
            int row = s >> 3;
            int c4 = (s & 7) * 4;
            cp_async16(&Ws[st][row][c4], &W[(size_t)(cbase + row) * D_MODEL + k0 + c4]);
        }
        CP_COMMIT();
    };

    prefetch(0);
    for (int c = 0; c < 8; c++) {
        const int st = c & 1;
        if (c < 7) { prefetch(c + 1); CP_WAIT1(); }
        else       { CP_WAIT0(); }
        __syncthreads();

        unsigned qa[4][4];
#pragma unroll
        for (int kk = 0; kk < 4; kk++) {
            qa[kk][0] = f2tf32(As[st][w16 + g    ][kk * 8 + t    ]);
            qa[kk][1] = f2tf32(As[st][w16 + g + 8][kk * 8 + t    ]);
            qa[kk][2] = f2tf32(As[st][w16 + g    ][kk * 8 + t + 4]);
            qa[kk][3] = f2tf32(As[st][w16 + g + 8][kk * 8 + t + 4]);
        }
#pragma unroll
        for (int n8 = 0; n8 < 8; n8++) {
#pragma unroll
            for (int kk = 0; kk < 4; kk++) {
                unsigned bb[2];
                bb[0] = f2tf32(Ws[st][n8 * 8 + g][kk * 8 + t    ]);
                bb[1] = f2tf32(Ws[st][n8 * 8 + g][kk * 8 + t + 4]);
                MMA_TF32(sc[n8], qa[kk], bb);
            }
        }
        __syncthreads();
    }

    const float scale = (z == 0) ? ATT_SCALE : 1.0f;
#pragma unroll
    for (int n8 = 0; n8 < 8; n8++) {
        int c0 = cbase + n8 * 8 + 2 * t;
        float b0v = bias[c0], b1v = bias[c0 + 1];
        int r0 = rbase + w16 + g;
        int r1 = r0 + 8;
        float2 v0, v1;
        v0.x = __uint_as_float(f2tf32((sc[n8][0] + b0v) * scale));
        v0.y = __uint_as_float(f2tf32((sc[n8][1] + b1v) * scale));
        v1.x = __uint_as_float(f2tf32((sc[n8][2] + b0v) * scale));
        v1.y = __uint_as_float(f2tf32((sc[n8][3] + b1v) * scale));
        int h = c0 >> 5, dk = c0 & 31;
        int b0i = r0 >> 10, n0 = r0 & 1023;
        int b1i = r1 >> 10, n1 = r1 & 1023;
        *(float2*)&out[(size_t)(((b0i << 3) + h) * N_SEQ + n0) * D_HEAD + dk] = v0;
        *(float2*)&out[(size_t)(((b1i << 3) + h) * N_SEQ + n1) * D_HEAD + dk] = v1;
    }
}

// ---------------------------------------------------------------------------
// Output projection, tf32 tensor cores, 2-stage cp.async pipeline.
// grid=(64,4), block=128. A = g_AO (already tf32-rounded).
// ---------------------------------------------------------------------------
__global__ __launch_bounds__(128) void gemm_o_tc(
    const float* __restrict__ W, const float* __restrict__ bias,
    float* __restrict__ out)
{
    __shared__ float As[2][64][36];
    __shared__ float Ws[2][64][36];

    const int tid  = threadIdx.x;
    const int lane = tid & 31;
    const int w    = tid >> 5;
    const int g    = lane >> 2;
    const int t    = lane & 3;
    const int w16  = w * 16;
    const int rbase = blockIdx.x * 64;
    const int cbase = blockIdx.y * 64;

    float sc[8][4];
#pragma unroll
    for (int n = 0; n < 8; n++)
#pragma unroll
        for (int j = 0; j < 4; j++) sc[n][j] = 0.0f;

    auto prefetch = [&](int c) {
        const int k0 = c * 32, st = c & 1;
#pragma unroll
        for (int it = 0; it < 4; it++) {
            int s = it * 128 + tid;
            int row = s >> 3;
            int c4 = (s & 7) * 4;
            cp_async16(&As[st][row][c4], &g_AO[(size_t)(rbase + row) * D_MODEL + k0 + c4]);
        }
#pragma unroll
        for (int it = 0; it < 4; it++) {
            int s = it * 128 + tid;
            int row = s >> 3;
            int c4 = (s & 7) * 4;
            cp_async16(&Ws[st][row][c4], &W[(size_t)(cbase + row) * D_MODEL + k0 + c4]);
        }
        CP_COMMIT();
    };

    prefetch(0);
    for (int c = 0; c < 8; c++) {
        const int st = c & 1;
        if (c < 7) { prefetch(c + 1); CP_WAIT1(); }
        else       { CP_WAIT0(); }
        __syncthreads();

        unsigned qa[4][4];
#pragma unroll
        for (int kk = 0; kk < 4; kk++) {
            qa[kk][0] = __float_as_uint(As[st][w16 + g    ][kk * 8 + t    ]);
            qa[kk][1] = __float_as_uint(As[st][w16 + g + 8][kk * 8 + t    ]);
            qa[kk][2] = __float_as_uint(As[st][w16 + g    ][kk * 8 + t + 4]);
            qa[kk][3] = __float_as_uint(As[st][w16 + g + 8][kk * 8 + t + 4]);
        }
#pragma unroll
        for (int n8 = 0; n8 < 8; n8++) {
#pragma unroll
            for (int kk = 0; kk < 4; kk++) {
                unsigned bb[2];
                bb[0] = f2tf32(Ws[st][n8 * 8 + g][kk * 8 + t    ]);
                bb[1] = f2tf32(Ws[st][n8 * 8 + g][kk * 8 + t + 4]);
                MMA_TF32(sc[n8], qa[kk], bb);
            }
        }
        __syncthreads();
    }

#pragma unroll
    for (int n8 = 0; n8 < 8; n8++) {
        int c0 = cbase + n8 * 8 + 2 * t;
        float b0v = bias[c0], b1v = bias[c0 + 1];
        int r0 = rbase + w16 + g;
        int r1 = r0 + 8;
        float2 v0, v1;
        v0.x = sc[n8][0] + b0v;  v0.y = sc[n8][1] + b1v;
        v1.x = sc[n8][2] + b0v;  v1.y = sc[n8][3] + b1v;
        *(float2*)&out[(size_t)r0 * D_MODEL + c0] = v0;
        *(float2*)&out[(size_t)r1 * D_MODEL + c0] = v1;
    }
}

// ---------------------------------------------------------------------------
// Tensor-core flash attention, TRIPLE-buffered cp.async pipeline: group(j)
// issued at end of tile j-3; wait_group 2 keeps TWO full groups (~143 KB)
// in flight during every tile's compute. grid=(16,32), block=128, 1 CTA/SM.
// Dynamic smem (floats):
//   KsB[3][64*36] @ 0      (6912)
//   VsB[3][64*40] @ 6912   (7680)
//   Ps  [64*68]   @ 14592  (4352)   (also Q staging in prologue)
//   Bias[3][3][64*64] @ 18944 (36864)   16B-chunk XOR swizzle, stride 64
//   Msk [1024]    @ 55808  (1024)
// total 56832 floats = 227328 B
// Bias swizzle: word offset(row, chunk, wi) = row*64 + ((chunk^(row&15))<<2) + wi
// ---------------------------------------------------------------------------
#define ATTN_SMEM_BYTES (56832 * 4)

__global__ __launch_bounds__(128) void attn_tc_kernel(
    const float* __restrict__ edge,
    const float* __restrict__ spat,
    const float* __restrict__ rnk)
{
    extern __shared__ float dsm[];
    float* KsB  = dsm;
    float* VsB  = dsm + 6912;
    float* Ps   = dsm + 14592;
    float* Bias = dsm + 18944;
    float* Msk  = dsm + 55808;

    const int tid  = threadIdx.x;
    const int lane = tid & 31;
    const int w    = tid >> 5;
    const int g    = lane >> 2;
    const int t    = lane & 3;
    const int qb   = blockIdx.x * 64;
    const int bh   = blockIdx.y;
    const int b    = bh >> 3;
    const int h    = bh & 7;
    const int w16  = w * 16;

    const float* Kg0 = g_K + (size_t)bh * N_SEQ * D_HEAD;
    const float* Vg0 = g_V + (size_t)bh * N_SEQ * D_HEAD;
    const float* maskp = g_maskval + b * N_SEQ;
    const float* eg0 = edge + ((size_t)bh * N_SEQ + qb) * N_SEQ;
    const float* sg0 = spat + ((size_t)bh * N_SEQ + qb) * N_SEQ;
    const float* rg0 = rnk  + ((size_t)bh * N_SEQ + qb) * N_SEQ;

    // issue full group (K, V, 3 biases) for k-tile i into slot i%3
    auto issue_group = [&](int i) {
        const int kb = i * 64;
        const int st = i % 3;
        const float* Kg = Kg0 + (size_t)kb * D_HEAD;
        const float* Vg = Vg0 + (size_t)kb * D_HEAD;
        float* Ka = KsB + st * 2304;
        float* Va = VsB + st * 2560;
#pragma unroll
        for (int it = 0; it < 4; it++) {
            int s = it * 128 + tid;
            int row = s >> 3;
            int c4 = (s & 7) * 4;
            cp_async16(&Ka[row * 36 + c4], &Kg[row * D_HEAD + c4]);
            cp_async16(&Va[row * 40 + c4], &Vg[row * D_HEAD + c4]);
        }
        float* bb = Bias + st * 12288;
        const float* eg = eg0 + kb;
        const float* sg = sg0 + kb;
        const float* rg = rg0 + kb;
#pragma unroll
        for (int it = 0; it < 8; it++) {
            int s = it * 128 + tid;
            int row = s >> 4;
            int ch = s & 15;
            int so = row * 64 + ((ch ^ (row & 15)) << 2);
            size_t go = (size_t)row * N_SEQ + ch * 4;
            cp_async16(&bb[so],        &eg[go]);
            cp_async16(&bb[4096 + so], &sg[go]);
            cp_async16(&bb[8192 + so], &rg[go]);
        }
        CP_COMMIT();
    };

    // ---- Prologue: group Gq (Q + mask), then G0, G1, G2 ----
    const float* Qg = g_Q + ((size_t)bh * N_SEQ + qb) * D_HEAD;
#pragma unroll
    for (int it = 0; it < 4; it++) {
        int s = it * 128 + tid;
        int row = s >> 3;
        int c4 = (s & 7) * 4;
        cp_async16(&Ps[row * 68 + c4], &Qg[row * D_HEAD + c4]);
    }
#pragma unroll
    for (int it = 0; it < 2; it++) {
        int idx = (it * 128 + tid) * 4;
        cp_async16(&Msk[idx], &maskp[idx]);
    }
    CP_COMMIT();
    issue_group(0);
    issue_group(1);
    issue_group(2);

    CP_WAIT3();   // Gq done; G0..G2 may be pending
    __syncthreads();

    unsigned qa[4][4];
#pragma unroll
    for (int kk = 0; kk < 4; kk++) {
        qa[kk][0] = __float_as_uint(Ps[(w16 + g    ) * 68 + kk * 8 + t    ]);
        qa[kk][1] = __float_as_uint(Ps[(w16 + g + 8) * 68 + kk * 8 + t    ]);
        qa[kk][2] = __float_as_uint(Ps[(w16 + g    ) * 68 + kk * 8 + t + 4]);
        qa[kk][3] = __float_as_uint(Ps[(w16 + g + 8) * 68 + kk * 8 + t + 4]);
    }
    __syncthreads();   // everyone has Q frags before Ps is reused for P

    float o[4][4];
#pragma unroll
    for (int n = 0; n < 4; n++)
#pragma unroll
        for (int j = 0; j < 4; j++) o[n][j] = 0.0f;

    float m0 = __int_as_float(0xff800000), m1 = m0;
    float l0 = 0.0f, l1 = 0.0f;

    for (int i = 0; i < 16; i++) {
        const int kb = i * 64;
        const int st = i % 3;
        float* Ks = KsB + st * 2304;
        float* Vs = VsB + st * 2560;
        float* bb = Bias + st * 12288;

        // 1. wait until group(i) complete; up to 2 newer groups stay in flight
        if (i <= 13)      { CP_WAIT2(); }
        else if (i == 14) { CP_WAIT1(); }
        else              { CP_WAIT0(); }
        __syncthreads();

        // 2. S = Q K^T (Q pre-scaled by ATT_SCALE)
        float sc[8][4];
#pragma unroll
        for (int n8 = 0; n8 < 8; n8++) {
            sc[n8][0] = sc[n8][1] = sc[n8][2] = sc[n8][3] = 0.0f;
#pragma unroll
            for (int kk = 0; kk < 4; kk++) {
                unsigned kb2[2];
                kb2[0] = __float_as_uint(Ks[(n8 * 8 + g) * 36 + kk * 8 + t    ]);
                kb2[1] = __float_as_uint(Ks[(n8 * 8 + g) * 36 + kk * 8 + t + 4]);
                MMA_TF32(sc[n8], qa[kk], kb2);
            }
        }

        // 3. combine biases (swizzled smem) + mask
        {
            const int r0i = w16 + g;
            const int r1i = w16 + g + 8;
            const int wi  = (2 * t) & 3;
#pragma unroll
            for (int n8 = 0; n8 < 8; n8++) {
                int ch = 2 * n8 + (t >> 1);
                int o0 = r0i * 64 + ((ch ^ (r0i & 15)) << 2) + wi;
                int o1 = r1i * 64 + ((ch ^ (r1i & 15)) << 2) + wi;
                float2 e0 = *(float2*)&bb[o0],        e1 = *(float2*)&bb[o1];
                float2 s0 = *(float2*)&bb[4096 + o0], s1 = *(float2*)&bb[4096 + o1];
                float2 r0 = *(float2*)&bb[8192 + o0], r1 = *(float2*)&bb[8192 + o1];
                float2 mk = *(float2*)&Msk[kb + n8 * 8 + 2 * t];
                sc[n8][0] += (e0.x + s0.x) + (r0.x + mk.x);
                sc[n8][1] += (e0.y + s0.y) + (r0.y + mk.y);
                sc[n8][2] += (e1.x + s1.x) + (r1.x + mk.x);
                sc[n8][3] += (e1.y + s1.y) + (r1.y + mk.y);
            }
        }

        // 4. online softmax
        float ml0 = sc[0][0], ml1 = sc[0][2];
#pragma unroll
        for (int n8 = 0; n8 < 8; n8++) {
            ml0 = fmaxf(ml0, fmaxf(sc[n8][0], sc[n8][1]));
            ml1 = fmaxf(ml1, fmaxf(sc[n8][2], sc[n8][3]));
        }
        ml0 = fmaxf(ml0, __shfl_xor_sync(0xffffffffu, ml0, 1));
        ml0 = fmaxf(ml0, __shfl_xor_sync(0xffffffffu, ml0, 2));
        ml1 = fmaxf(ml1, __shfl_xor_sync(0xffffffffu, ml1, 1));
        ml1 = fmaxf(ml1, __shfl_xor_sync(0xffffffffu, ml1, 2));

        float mn0 = fmaxf(m0, ml0);
        float mn1 = fmaxf(m1, ml1);
        float mc0 = fmaxf(mn0, -1e30f);
        float mc1 = fmaxf(mn1, -1e30f);
        float rs0 = __expf(fmaxf(m0, -1e30f) - mc0);
        float rs1 = __expf(fmaxf(m1, -1e30f) - mc1);
        m0 = mn0; m1 = mn1;

        float sum0 = 0.0f, sum1 = 0.0f;
#pragma unroll
        for (int n8 = 0; n8 < 8; n8++) {
            float p0 = __expf(sc[n8][0] - mc0);
            float p1 = __expf(sc[n8][1] - mc0);
            float p2 = __expf(sc[n8][2] - mc1);
            float p3 = __expf(sc[n8][3] - mc1);
            sum0 += p0 + p1;
            sum1 += p2 + p3;
            float2 w0, w1;
            w0.x = __uint_as_float(f2tf32(p0)); w0.y = __uint_as_float(f2tf32(p1));
            w1.x = __uint_as_float(f2tf32(p2)); w1.y = __uint_as_float(f2tf32(p3));
            *(float2*)&Ps[(w16 + g    ) * 68 + n8 * 8 + 2 * t] = w0;
            *(float2*)&Ps[(w16 + g + 8) * 68 + n8 * 8 + 2 * t] = w1;
        }
        sum0 += __shfl_xor_sync(0xffffffffu, sum0, 1);
        sum0 += __shfl_xor_sync(0xffffffffu, sum0, 2);
        sum1 += __shfl_xor_sync(0xffffffffu, sum1, 1);
        sum1 += __shfl_xor_sync(0xffffffffu, sum1, 2);
        l0 = l0 * rs0 + sum0;
        l1 = l1 * rs1 + sum1;

#pragma unroll
        for (int n = 0; n < 4; n++) {
            o[n][0] *= rs0; o[n][1] *= rs0;
            o[n][2] *= rs1; o[n][3] *= rs1;
        }

        __syncwarp();   // this warp's Ps rows visible warp-wide

        // 5. O += P V
#pragma unroll
        for (int kk = 0; kk < 8; kk++) {
            unsigned pa[4];
            pa[0] = __float_as_uint(Ps[(w16 + g    ) * 68 + kk * 8 + t    ]);
            pa[1] = __float_as_uint(Ps[(w16 + g + 8) * 68 + kk * 8 + t    ]);
            pa[2] = __float_as_uint(Ps[(w16 + g    ) * 68 + kk * 8 + t + 4]);
            pa[3] = __float_as_uint(Ps[(w16 + g + 8) * 68 + kk * 8 + t + 4]);
#pragma unroll
            for (int n = 0; n < 4; n++) {
                unsigned vb[2];
                vb[0] = __float_as_uint(Vs[(kk * 8 + t    ) * 40 + n * 8 + g]);
                vb[1] = __float_as_uint(Vs[(kk * 8 + t + 4) * 40 + n * 8 + g]);
                MMA_TF32(o[n], pa, vb);
            }
        }

        // 6. slot i%3 fully consumed by all warps -> refill with group(i+3)
        __syncthreads();
        if (i + 3 <= 15) issue_group(i + 3);
    }

    // normalize + scatter (tf32-rounded for the O-projection mma)
    float inv0 = (l0 > 0.0f) ? (1.0f / l0) : 0.0f;
    float inv1 = (l1 > 0.0f) ? (1.0f / l1) : 0.0f;
    const int r0 = qb + w16 + g;
    const int r1 = r0 + 8;
#pragma unroll
    for (int n = 0; n < 4; n++) {
        int d = n * 8 + 2 * t;
        float2 v0, v1;
        v0.x = __uint_as_float(f2tf32(o[n][0] * inv0));
        v0.y = __uint_as_float(f2tf32(o[n][1] * inv0));
        v1.x = __uint_as_float(f2tf32(o[n][2] * inv1));
        v1.y = __uint_as_float(f2tf32(o[n][3] * inv1));
        *(float2*)&g_AO[((size_t)(b * N_SEQ + r0)) * D_MODEL + h * D_HEAD + d] = v0;
        *(float2*)&g_AO[((size_t)(b * N_SEQ + r1)) * D_MODEL + h * D_HEAD + d] = v1;
    }
}

// ---------------------------------------------------------------------------
extern "C" void kernel_launch(void* const* d_in, const int* in_sizes, int n_in,
                              void* d_out, int out_size)
{
    const float* x    = (const float*)d_in[0];
    const float* edge = (const float*)d_in[1];
    const float* spat = (const float*)d_in[2];
    const float* rnk  = (const float*)d_in[3];
    const void*  mask = d_in[4];
    const float* Wq = (const float*)d_in[5];
    const float* bq = (const float*)d_in[6];
    const float* Wk = (const float*)d_in[7];
    const float* bk = (const float*)d_in[8];
    const float* Wv = (const float*)d_in[9];
    const float* bv = (const float*)d_in[10];
    const float* Wo = (const float*)d_in[11];
    const float* bo = (const float*)d_in[12];

    cudaFuncSetAttribute(attn_tc_kernel,
                         cudaFuncAttributeMaxDynamicSharedMemorySize,
                         ATTN_SMEM_BYTES);

    prep_mask_kernel<<<1, 256>>>(mask);

    gemm_qkv_tc<<<dim3(64, 4, 3), 128>>>(x, Wq, Wk, Wv, bq, bk, bv);

    attn_tc_kernel<<<dim3(16, 32), 128, ATTN_SMEM_BYTES>>>(edge, spat, rnk);

    gemm_o_tc<<<dim3(64, 4), 128>>>(Wo, bo, (float*)d_out);
}